// round 1
// baseline (speedup 1.0000x reference)
#include <cuda_runtime.h>

#define NN  3072
#define EE  3072
#define ELG 6144
#define FF  64
#define HH  4

// -------- scratch (__device__ globals; no allocations allowed) --------
__device__ float g_NQ[NN*HH*FF];
__device__ float g_NV[NN*HH*FF];
__device__ float g_EQ[EE*HH*FF];
__device__ float g_EV[EE*HH*FF];
__device__ float g_NK[NN*HH];
__device__ float g_EK[EE*HH];
__device__ float g_srk[2*HH*FF];
__device__ float g_natt[HH*NN];
__device__ float g_eatt[HH*EE];
__device__ int   g_keyN[EE];
__device__ int   g_keyL[ELG];
__device__ unsigned char g_winN[EE];
__device__ unsigned char g_winL[ELG];

// -------- K0: zero output + srk accumulators, build dedup keys --------
__global__ void k_init(float* out, const int* src, const int* dst,
                       const int* lgs, const int* lgd) {
    int i = blockIdx.x * blockDim.x + threadIdx.x;
    if (i < (NN + EE) * FF) out[i] = 0.f;
    if (i < 2 * HH * FF)    g_srk[i] = 0.f;
    if (i < EE)             g_keyN[i] = src[i] * NN + dst[i];
    if (i < ELG)            g_keyL[i] = lgs[i] * EE + lgd[i];
}

// -------- K1: big projections  [3072x64] @ [64x256] + bias (x4) --------
// 64x64 tile / 4x4 per thread, 256 threads, A transposed in smem (pad 65).
__global__ void __launch_bounds__(256) k_gemm_big(
    const float* nin, const float* ein,
    const float* nqW, const float* nqb, const float* nvW, const float* nvb,
    const float* eqW, const float* eqb, const float* evW, const float* evb)
{
    __shared__ float As[64 * 65];
    __shared__ float Ws[64 * 64];
    __shared__ float Bs[64];

    const float *in, *W, *b;
    float* out;
    switch (blockIdx.z) {
        case 0:  in = nin; W = nqW; b = nqb; out = g_NQ; break;
        case 1:  in = nin; W = nvW; b = nvb; out = g_NV; break;
        case 2:  in = ein; W = eqW; b = eqb; out = g_EQ; break;
        default: in = ein; W = evW; b = evb; out = g_EV; break;
    }
    int tid = threadIdx.x;
    int r0 = blockIdx.x * 64;
    int c0 = blockIdx.y * 64;

    #pragma unroll
    for (int i = 0; i < 16; i++) {             // A tile, transposed store
        int idx = i * 256 + tid;
        int r = idx >> 6, k = idx & 63;
        As[k * 65 + r] = in[r0 * 64 + idx];    // fully coalesced LDG
    }
    #pragma unroll
    for (int i = 0; i < 16; i++) {             // W tile
        int idx = i * 256 + tid;
        int k = idx >> 6, c = idx & 63;
        Ws[k * 64 + c] = W[k * 256 + c0 + c];
    }
    if (tid < 64) Bs[tid] = b[c0 + tid];
    __syncthreads();

    int tx = tid & 15, ty = tid >> 4;
    int rl = ty * 4, cl = tx * 4;
    float acc[4][4];
    #pragma unroll
    for (int i = 0; i < 4; i++)
        #pragma unroll
        for (int j = 0; j < 4; j++) acc[i][j] = Bs[cl + j];

    #pragma unroll 16
    for (int k = 0; k < 64; k++) {
        float a0 = As[k * 65 + rl + 0];
        float a1 = As[k * 65 + rl + 1];
        float a2 = As[k * 65 + rl + 2];
        float a3 = As[k * 65 + rl + 3];
        float4 w = *(const float4*)&Ws[k * 64 + cl];
        acc[0][0] += a0 * w.x; acc[0][1] += a0 * w.y; acc[0][2] += a0 * w.z; acc[0][3] += a0 * w.w;
        acc[1][0] += a1 * w.x; acc[1][1] += a1 * w.y; acc[1][2] += a1 * w.z; acc[1][3] += a1 * w.w;
        acc[2][0] += a2 * w.x; acc[2][1] += a2 * w.y; acc[2][2] += a2 * w.z; acc[2][3] += a2 * w.w;
        acc[3][0] += a3 * w.x; acc[3][1] += a3 * w.y; acc[3][2] += a3 * w.z; acc[3][3] += a3 * w.w;
    }
    #pragma unroll
    for (int i = 0; i < 4; i++) {
        float4 v = make_float4(acc[i][0], acc[i][1], acc[i][2], acc[i][3]);
        *(float4*)&out[(r0 + rl + i) * 256 + c0 + cl] = v;
    }
}

// -------- K2: tiny projections [3072x64] @ [64x4] + bias (x2) --------
__global__ void __launch_bounds__(256) k_gemm_small(
    const float* nin, const float* ein,
    const float* nkW, const float* nkb, const float* ekW, const float* ekb)
{
    __shared__ float s_in[64 * 65];
    __shared__ float sW[64 * 4];
    __shared__ float sb[4];
    const float* in = blockIdx.y ? ein : nin;
    const float* W  = blockIdx.y ? ekW : nkW;
    const float* b  = blockIdx.y ? ekb : nkb;
    float* out      = blockIdx.y ? g_EK : g_NK;

    int tid = threadIdx.x;
    int r0 = blockIdx.x * 64;
    #pragma unroll
    for (int i = 0; i < 16; i++) {
        int idx = i * 256 + tid;
        int r = idx >> 6, k = idx & 63;
        s_in[r * 65 + k] = in[r0 * 64 + idx];
    }
    sW[tid & 255] = W[tid & 255];  // 256 threads load 256 weights
    if (tid < 4) sb[tid] = b[tid];
    __syncthreads();

    int rl = tid >> 2, c = tid & 3;
    float acc = sb[c];
    #pragma unroll 16
    for (int k = 0; k < 64; k++)
        acc += s_in[rl * 65 + k] * sW[k * 4 + c];
    out[(r0 + rl) * 4 + c] = acc;
}

// -------- K3: srk[h][f] = sum_n input[n][f] * k[h*M+n] --------
__global__ void k_srk(const float* nin, const float* ein) {
    int chunk = blockIdx.x;            // 16 chunks of 192 rows
    int h = blockIdx.y, g = blockIdx.z;
    const float* in = g ? ein : nin;
    const float* kb = g ? g_EK : g_NK;
    int f = threadIdx.x;               // 64 lanes
    float acc = 0.f;
    int n0 = chunk * 192;
    #pragma unroll 4
    for (int n = n0; n < n0 + 192; n++)
        acc += in[n * 64 + f] * __ldg(&kb[h * 3072 + n]);
    atomicAdd(&g_srk[(g * 4 + h) * 64 + f], acc);
}

// -------- K4: logits + softmax per (head, graph) --------
__global__ void __launch_bounds__(1024) k_att() {
    __shared__ float s_x[3072];
    __shared__ float s_srk[64];
    __shared__ float s_red[32];
    __shared__ float s_bval;

    int h = blockIdx.x, g = blockIdx.y;
    const float* q = g ? g_EQ : g_NQ;
    float* att     = g ? g_eatt : g_natt;
    int tid = threadIdx.x;
    if (tid < 64) s_srk[tid] = g_srk[(g * 4 + h) * 64 + tid];
    __syncthreads();

    int lane = tid & 31, w = tid >> 5;
    float lmax = -1e30f;
    for (int i = 0; i < 96; i++) {
        int n = w * 96 + i;
        const float* qr = q + (size_t)(h * 3072 + n) * 64;
        float p = qr[lane] * s_srk[lane] + qr[lane + 32] * s_srk[lane + 32];
        #pragma unroll
        for (int o = 16; o > 0; o >>= 1) p += __shfl_down_sync(0xffffffffu, p, o);
        if (lane == 0) {
            float x = p * 0.125f;   // / sqrt(64)
            s_x[n] = x;
            lmax = fmaxf(lmax, x);
        }
    }
    lmax = __shfl_sync(0xffffffffu, lmax, 0);
    if (lane == 0) s_red[w] = lmax;
    __syncthreads();
    if (w == 0) {
        float m = s_red[lane];
        #pragma unroll
        for (int o = 16; o > 0; o >>= 1) m = fmaxf(m, __shfl_down_sync(0xffffffffu, m, o));
        if (lane == 0) s_bval = m;
    }
    __syncthreads();
    float mx = s_bval;

    float lsum = 0.f;
    #pragma unroll
    for (int i = 0; i < 3; i++) {
        int n = tid + i * 1024;
        float e = __expf(s_x[n] - mx);
        s_x[n] = e;
        lsum += e;
    }
    #pragma unroll
    for (int o = 16; o > 0; o >>= 1) lsum += __shfl_down_sync(0xffffffffu, lsum, o);
    __syncthreads();
    if (lane == 0) s_red[w] = lsum;
    __syncthreads();
    if (tid == 0) {
        float s = 0.f;
        #pragma unroll
        for (int i = 0; i < 32; i++) s += s_red[i];
        s_bval = 1.f / s;
    }
    __syncthreads();
    float inv = s_bval;
    #pragma unroll
    for (int i = 0; i < 3; i++) {
        int n = tid + i * 1024;
        att[h * 3072 + n] = s_x[n] * inv;
    }
}

// -------- K5: dedup winners (last-write-wins => max index per key) --------
__global__ void __launch_bounds__(512) k_win() {
    int kind = blockIdx.y;
    int M = kind ? ELG : EE;
    const int* key = kind ? g_keyL : g_keyN;
    unsigned char* win = kind ? g_winL : g_winN;

    int tid = threadIdx.x;
    int e = blockIdx.x * 32 + (tid >> 4);
    if (blockIdx.x * 32 >= M) return;          // whole block out of range
    int s = tid & 15;
    int ke = key[e];
    bool lose = false;
    for (int j = e + 1 + s; j < M; j += 16)
        lose |= (key[j] == ke);
    unsigned bal = __ballot_sync(0xffffffffu, lose);
    unsigned gmask = 0xffffu << (tid & 16);
    if (s == 0) win[e] = ((bal & gmask) == 0) ? 1 : 0;
}

// -------- K6: message passing scatter (node + line-graph) --------
__global__ void __launch_bounds__(256) k_scatter(
    const int* src, const int* dst, const int* lgs, const int* lgd, float* out)
{
    int tid = threadIdx.x;
    int u = tid >> 6, f = tid & 63;
    int bx = blockIdx.x;
    if (bx < 768) {                                    // node messages
        int e = bx * 4 + u;
        if (!g_winN[e]) return;
        int s = src[e], d = dst[e];
        float acc = 0.f;
        #pragma unroll
        for (int h = 0; h < 4; h++)
            acc += g_eatt[h * 3072 + e] * g_NV[((size_t)(h * 3072 + d)) * 64 + f];
        atomicAdd(&out[s * 64 + f], 0.25f * acc);      // mean over heads
    } else {                                           // line-graph messages
        int l = (bx - 768) * 4 + u;
        if (!g_winL[l]) return;
        int e1 = lgs[l], e2 = lgd[l];
        int c = dst[e1];
        float acc = 0.f;
        #pragma unroll
        for (int h = 0; h < 4; h++)
            acc += g_natt[h * 3072 + c] * g_EV[((size_t)(h * 3072 + e2)) * 64 + f];
        atomicAdd(&out[NN * 64 + e1 * 64 + f], 0.25f * acc);
    }
}

extern "C" void kernel_launch(void* const* d_in, const int* in_sizes, int n_in,
                              void* d_out, int out_size)
{
    const float* nin = (const float*)d_in[0];
    const float* ein = (const float*)d_in[1];
    const int* src = (const int*)d_in[2];
    const int* dst = (const int*)d_in[3];
    const int* lgs = (const int*)d_in[4];
    const int* lgd = (const int*)d_in[5];
    const float* nqW = (const float*)d_in[6];  const float* nqb = (const float*)d_in[7];
    const float* nkW = (const float*)d_in[8];  const float* nkb = (const float*)d_in[9];
    const float* nvW = (const float*)d_in[10]; const float* nvb = (const float*)d_in[11];
    const float* eqW = (const float*)d_in[12]; const float* eqb = (const float*)d_in[13];
    const float* ekW = (const float*)d_in[14]; const float* ekb = (const float*)d_in[15];
    const float* evW = (const float*)d_in[16]; const float* evb = (const float*)d_in[17];
    float* out = (float*)d_out;

    k_init<<<1536, 256>>>(out, src, dst, lgs, lgd);

    dim3 gb(48, 4, 4);
    k_gemm_big<<<gb, 256>>>(nin, ein, nqW, nqb, nvW, nvb, eqW, eqb, evW, evb);

    dim3 gs(48, 2);
    k_gemm_small<<<gs, 256>>>(nin, ein, nkW, nkb, ekW, ekb);

    dim3 gr(16, 4, 2);
    k_srk<<<gr, 64>>>(nin, ein);

    dim3 ga(4, 2);
    k_att<<<ga, 1024>>>();

    dim3 gw(192, 2);
    k_win<<<gw, 512>>>();

    k_scatter<<<2304, 256>>>(src, dst, lgs, lgd, out);
}

// round 2
// speedup vs baseline: 1.5842x; 1.5842x over previous
#include <cuda_runtime.h>

#define NN   3072
#define EE   3072
#define ELG  6144
#define FF   64
#define HH   4
#define RPH  768   // input rows per head after .view scramble

// -------- scratch (__device__ globals; no allocations allowed) --------
__device__ float g_NV[NN * 256];
__device__ float g_EV[EE * 256];
__device__ float g_srkp[2 * 48 * 4 * 64];   // partial srk sums [g][chunk][h][f]
__device__ float g_WT[2 * 256 * 64];        // transposed Wq (node, edge)
__device__ float g_c[2 * 4 * 4 * 64];       // c[g][h][j][k]
__device__ float g_d[2 * 4 * 4];            // d[g][h][j]
__device__ float g_logit[2 * 4 * 3072];
__device__ float g_att[2 * 4 * 3072];       // g=0: node att, g=1: edge att
__device__ unsigned char g_winN[EE];
__device__ unsigned char g_winL[ELG];

// ======================= kernel A: all input-only work =======================
// roles by blockIdx.x:
//   [0,96)        srk partials (fused K projection, never materialized)
//   [96,480)      V gemms: NV (192 blocks), EV (192 blocks)
//   [480,1056)    dedup winners: node (192), line-graph (384)
//   [1056,1440)   zero output
//   [1440,1448)   transpose Wq (node 4 tiles, edge 4 tiles)
__global__ void __launch_bounds__(256) kA(
    const float* nin, const float* ein,
    const float* nkW, const float* nkb, const float* ekW, const float* ekb,
    const float* nvW, const float* nvb, const float* evW, const float* evb,
    const float* nqW, const float* eqW,
    const int* src, const int* dst, const int* lgs, const int* lgd,
    float* out)
{
    __shared__ float sm[64 * 65 + 64 * 64 + 64];   // 33.8KB, unioned per role
    int b = blockIdx.x, tid = threadIdx.x;

    if (b < 96) {
        // ---- srk role: chunk of 64 nodes (16 KM rows per head) ----
        int g = b / 48, chunk = b % 48;
        const float* in = g ? ein : nin;
        const float* W  = g ? ekW : nkW;
        const float* bk = g ? ekb : nkb;
        float* s_in4 = sm;           // 4 * 16 * 65 = 4160
        float* s_km  = sm + 4224;    // 4 * 64

        #pragma unroll
        for (int h2 = 0; h2 < 4; h2++) {
            #pragma unroll
            for (int i = 0; i < 4; i++) {
                int idx = i * 256 + tid;
                int rr = idx >> 6, kk = idx & 63;
                s_in4[h2 * 1040 + rr * 65 + kk] =
                    in[(h2 * RPH + chunk * 16 + rr) * 64 + kk];
            }
        }
        __syncthreads();
        // phase 1: KM entries: k[h, n] = KM[h*768 + n/4, n%4]
        int h = tid >> 6, idx = tid & 63;
        int rl = idx >> 2, c = idx & 3;
        float acc = bk[c];
        #pragma unroll
        for (int k = 0; k < 64; k++)
            acc += s_in4[h * 1040 + rl * 65 + k] * W[k * 4 + c];
        s_km[h * 64 + rl * 4 + c] = acc;   // index == h*64 + local n
        __syncthreads();
        // phase 2: srk partial: srk[h,f] += in[n,f] * k[h,n] over 64 n
        int f = tid & 63;
        float sacc = 0.f;
        int n0 = chunk * 64;
        #pragma unroll 8
        for (int nl = 0; nl < 64; nl++)
            sacc += in[(n0 + nl) * 64 + f] * s_km[h * 64 + nl];
        g_srkp[((g * 48 + chunk) * 4 + h) * 64 + f] = sacc;

    } else if (b < 480) {
        // ---- V gemm role: [3072x64] @ [64x256] + bias ----
        int i2 = b - 96;
        int mat = i2 / 192;
        int rem = i2 % 192;
        int r0 = (rem >> 2) * 64, c0 = (rem & 3) * 64;
        const float* in = mat ? ein : nin;
        const float* W  = mat ? evW : nvW;
        const float* bb = mat ? evb : nvb;
        float* outv     = mat ? g_EV : g_NV;
        float* As = sm;                  // 64*65
        float* Ws = sm + 64 * 65;        // 64*64
        float* Bs = sm + 64 * 65 + 64 * 64;

        #pragma unroll
        for (int i = 0; i < 16; i++) {
            int idx = i * 256 + tid;
            int r = idx >> 6, k = idx & 63;
            As[k * 65 + r] = in[r0 * 64 + idx];
        }
        #pragma unroll
        for (int i = 0; i < 16; i++) {
            int idx = i * 256 + tid;
            int k = idx >> 6, cc = idx & 63;
            Ws[k * 64 + cc] = W[k * 256 + c0 + cc];
        }
        if (tid < 64) Bs[tid] = bb[c0 + tid];
        __syncthreads();

        int tx = tid & 15, ty = tid >> 4;
        int rl = ty * 4, cl = tx * 4;
        float acc[4][4];
        #pragma unroll
        for (int i = 0; i < 4; i++)
            #pragma unroll
            for (int j = 0; j < 4; j++) acc[i][j] = Bs[cl + j];

        #pragma unroll 16
        for (int k = 0; k < 64; k++) {
            float a0 = As[k * 65 + rl + 0];
            float a1 = As[k * 65 + rl + 1];
            float a2 = As[k * 65 + rl + 2];
            float a3 = As[k * 65 + rl + 3];
            float4 w = *(const float4*)&Ws[k * 64 + cl];
            acc[0][0] += a0 * w.x; acc[0][1] += a0 * w.y; acc[0][2] += a0 * w.z; acc[0][3] += a0 * w.w;
            acc[1][0] += a1 * w.x; acc[1][1] += a1 * w.y; acc[1][2] += a1 * w.z; acc[1][3] += a1 * w.w;
            acc[2][0] += a2 * w.x; acc[2][1] += a2 * w.y; acc[2][2] += a2 * w.z; acc[2][3] += a2 * w.w;
            acc[3][0] += a3 * w.x; acc[3][1] += a3 * w.y; acc[3][2] += a3 * w.z; acc[3][3] += a3 * w.w;
        }
        #pragma unroll
        for (int i = 0; i < 4; i++) {
            float4 v = make_float4(acc[i][0], acc[i][1], acc[i][2], acc[i][3]);
            *(float4*)&outv[(r0 + rl + i) * 256 + c0 + cl] = v;
        }

    } else if (b < 1056) {
        // ---- dedup winner role: last-write-wins => max index per key ----
        int i2 = b - 480;
        const int *ka, *kb2; int M; unsigned char* win; int e0;
        if (i2 < 192) { ka = src; kb2 = dst; M = EE;  win = g_winN; e0 = i2 * 16; }
        else { i2 -= 192; ka = lgs; kb2 = lgd; M = ELG; win = g_winL; e0 = i2 * 16; }
        int e = e0 + (tid >> 4);
        int s = tid & 15;
        int ke = ka[e] * 8192 + kb2[e];
        bool lose = false;
        #pragma unroll 4
        for (int j = e + 1 + s; j < M; j += 16)
            lose |= (ka[j] * 8192 + kb2[j] == ke);
        unsigned bal = __ballot_sync(0xffffffffu, lose);
        unsigned gm = 0xffffu << (tid & 16);
        if (s == 0) win[e] = ((bal & gm) == 0) ? 1 : 0;

    } else if (b < 1440) {
        // ---- zero output ----
        int idx = (b - 1056) * 256 + tid;
        ((float4*)out)[idx] = make_float4(0.f, 0.f, 0.f, 0.f);

    } else {
        // ---- transpose Wq: [64k][256c] -> WT[256c][64k] ----
        int t = b - 1440;
        int mat = t >> 2, tile = t & 3;
        const float* W = mat ? eqW : nqW;
        float* s = sm;   // 64*65
        #pragma unroll
        for (int i = 0; i < 16; i++) {
            int idx = i * 256 + tid;
            int k = idx >> 6, c = idx & 63;
            s[k * 65 + c] = W[k * 256 + tile * 64 + c];
        }
        __syncthreads();
        #pragma unroll
        for (int i = 0; i < 16; i++) {
            int idx = i * 256 + tid;
            int c = idx >> 6, k = idx & 63;
            g_WT[mat * 16384 + (tile * 64 + c) * 64 + k] = s[k * 65 + c];
        }
    }
}

// ============ kernel B: reduce srk, compute c[g][h][j][k], d[g][h][j] ============
__global__ void __launch_bounds__(256) kB(
    const float* nqb, const float* eqb)
{
    __shared__ float s_part[256];
    __shared__ float s_srk[64];
    int b = blockIdx.x;          // 8 blocks: g = b>>2, h = b&3
    int g = b >> 2, h = b & 3;
    int tid = threadIdx.x;

    int q = tid >> 6, f = tid & 63;
    float a = 0.f;
    #pragma unroll
    for (int p = 0; p < 12; p++)
        a += g_srkp[((g * 48 + q * 12 + p) * 4 + h) * 64 + f];
    s_part[tid] = a;
    __syncthreads();
    if (tid < 64)
        s_srk[tid] = s_part[tid] + s_part[64 + tid] + s_part[128 + tid] + s_part[192 + tid];
    __syncthreads();

    // c[j][k] = sum_f Wq[k, 64j+f] * srk[f]  (coalesced via WT)
    int j = tid & 3, k = tid >> 2;
    const float* wt = g_WT + g * 16384 + j * 64 * 64;   // WT[(j*64+f)*64 + k]
    float a2 = 0.f;
    #pragma unroll
    for (int f2 = 0; f2 < 64; f2++)
        a2 += wt[f2 * 64 + k] * s_srk[f2];
    g_c[((g * 4 + h) * 4 + j) * 64 + k] = a2;

    if (tid < 4) {
        const float* bq = g ? eqb : nqb;
        float dd = 0.f;
        #pragma unroll
        for (int f2 = 0; f2 < 64; f2++) dd += bq[tid * 64 + f2] * s_srk[f2];
        g_d[(g * 4 + h) * 4 + tid] = dd;
    }
}

// ======================= kernel C: logits =======================
__global__ void __launch_bounds__(256) kC(
    const float* nin, const float* ein)
{
    __shared__ float s_c[4 * 65];
    __shared__ float s_d[4];
    __shared__ float s_in[64 * 65];

    int b = blockIdx.x;                  // 96: g(2) x h(4) x chunk(12)
    int g = b / 48;
    int h = (b % 48) / 12;
    int chunk = b % 12;
    const float* in = g ? ein : nin;
    int tid = threadIdx.x;

    {
        int j = tid >> 6, k = tid & 63;
        s_c[j * 65 + k] = g_c[((g * 4 + h) * 4 + j) * 64 + k];
        if (tid < 4) s_d[tid] = g_d[(g * 4 + h) * 4 + tid];
    }
    {
        int base = (h * RPH + chunk * 64) * 64;
        #pragma unroll
        for (int i = 0; i < 16; i++) {
            int idx = i * 256 + tid;
            s_in[(idx >> 6) * 65 + (idx & 63)] = in[base + idx];
        }
    }
    __syncthreads();

    int m = tid >> 2, j = tid & 3;
    float lg = s_d[j];
    #pragma unroll
    for (int k = 0; k < 64; k++)
        lg += s_in[m * 65 + k] * s_c[j * 65 + k];
    lg *= 0.125f;   // / sqrt(64)
    int n = (chunk * 64 + m) * 4 + j;
    g_logit[(g * 4 + h) * 3072 + n] = lg;
}

// ======================= kernel C2: softmax =======================
__global__ void __launch_bounds__(1024) kC2() {
    __shared__ float s_e[3072];
    __shared__ float s_red[32];
    __shared__ float s_v;
    int g = blockIdx.x >> 2, h = blockIdx.x & 3;
    int tid = threadIdx.x;
    const float* lg = g_logit + (g * 4 + h) * 3072;
    float* att = g_att + (g * 4 + h) * 3072;

    float x0 = lg[tid], x1 = lg[tid + 1024], x2 = lg[tid + 2048];
    float mx = fmaxf(x0, fmaxf(x1, x2));
    #pragma unroll
    for (int o = 16; o > 0; o >>= 1) mx = fmaxf(mx, __shfl_xor_sync(0xffffffffu, mx, o));
    if ((tid & 31) == 0) s_red[tid >> 5] = mx;
    __syncthreads();
    if (tid == 0) {
        float m2 = s_red[0];
        #pragma unroll
        for (int i = 1; i < 32; i++) m2 = fmaxf(m2, s_red[i]);
        s_v = m2;
    }
    __syncthreads();
    float m = s_v;
    float e0 = __expf(x0 - m), e1 = __expf(x1 - m), e2 = __expf(x2 - m);
    s_e[tid] = e0; s_e[tid + 1024] = e1; s_e[tid + 2048] = e2;
    float lsum = e0 + e1 + e2;
    #pragma unroll
    for (int o = 16; o > 0; o >>= 1) lsum += __shfl_xor_sync(0xffffffffu, lsum, o);
    __syncthreads();
    if ((tid & 31) == 0) s_red[tid >> 5] = lsum;
    __syncthreads();
    if (tid == 0) {
        float s = 0.f;
        #pragma unroll
        for (int i = 0; i < 32; i++) s += s_red[i];
        s_v = 1.f / s;
    }
    __syncthreads();
    float inv = s_v;
    att[tid] = s_e[tid] * inv;
    att[tid + 1024] = s_e[tid + 1024] * inv;
    att[tid + 2048] = s_e[tid + 2048] * inv;
}

// ======================= kernel D: message-passing scatter =======================
__global__ void __launch_bounds__(256) kD(
    const int* src, const int* dst, const int* lgs, const int* lgd, float* out)
{
    int tid = threadIdx.x;
    int u = tid >> 6, f = tid & 63;
    int bx = blockIdx.x;
    if (bx < 768) {                                    // node messages (use edge att, g=1)
        int e = bx * 4 + u;
        if (!g_winN[e]) return;
        int s = src[e], d = dst[e];
        float acc = 0.f;
        #pragma unroll
        for (int h = 0; h < 4; h++)
            acc += g_att[(4 + h) * 3072 + e] * g_NV[((size_t)(h * 3072 + d)) * 64 + f];
        atomicAdd(&out[s * 64 + f], 0.25f * acc);      // mean over heads
    } else {                                           // line-graph messages (use node att, g=0)
        int l = (bx - 768) * 4 + u;
        if (!g_winL[l]) return;
        int e1 = lgs[l], e2 = lgd[l];
        int c = dst[e1];
        float acc = 0.f;
        #pragma unroll
        for (int h = 0; h < 4; h++)
            acc += g_att[h * 3072 + c] * g_EV[((size_t)(h * 3072 + e2)) * 64 + f];
        atomicAdd(&out[NN * 64 + e1 * 64 + f], 0.25f * acc);
    }
}

extern "C" void kernel_launch(void* const* d_in, const int* in_sizes, int n_in,
                              void* d_out, int out_size)
{
    const float* nin = (const float*)d_in[0];
    const float* ein = (const float*)d_in[1];
    const int* src = (const int*)d_in[2];
    const int* dst = (const int*)d_in[3];
    const int* lgs = (const int*)d_in[4];
    const int* lgd = (const int*)d_in[5];
    const float* nqW = (const float*)d_in[6];  const float* nqb = (const float*)d_in[7];
    const float* nkW = (const float*)d_in[8];  const float* nkb = (const float*)d_in[9];
    const float* nvW = (const float*)d_in[10]; const float* nvb = (const float*)d_in[11];
    const float* eqW = (const float*)d_in[12]; const float* eqb = (const float*)d_in[13];
    const float* ekW = (const float*)d_in[14]; const float* ekb = (const float*)d_in[15];
    const float* evW = (const float*)d_in[16]; const float* evb = (const float*)d_in[17];
    float* out = (float*)d_out;

    kA<<<1448, 256>>>(nin, ein, nkW, nkb, ekW, ekb, nvW, nvb, evW, evb,
                      nqW, eqW, src, dst, lgs, lgd, out);
    kB<<<8, 256>>>(nqb, eqb);
    kC<<<96, 256>>>(nin, ein);
    kC2<<<8, 1024>>>();
    kD<<<2304, 256>>>(src, dst, lgs, lgd, out);
}